// round 11
// baseline (speedup 1.0000x reference)
#include <cuda_runtime.h>
#include <cuda_bf16.h>
#include <cstdint>

// Problem constants
#define BATCH   2
#define SEQ     2048
#define DMODEL  1024
#define NHEADS  16
#define HDIM    64
#define MTOT    (BATCH * SEQ)          // 4096

// Scratch (device globals; no allocations allowed)
__device__ float g_Q[BATCH * NHEADS * SEQ * HDIM];     // [b,h,s,d] tf32 bits
__device__ float g_K[BATCH * NHEADS * SEQ * HDIM];
__device__ float g_V[BATCH * NHEADS * SEQ * HDIM];
__device__ float g_attn[MTOT * DMODEL];                // [b*s, h*d] tf32 bits
__device__ float g_Xq[MTOT * DMODEL];                  // rounded inputs
__device__ float g_Xk[MTOT * DMODEL];
__device__ float g_Xv[MTOT * DMODEL];
__device__ float g_WTq[DMODEL * DMODEL];               // W^T, rounded
__device__ float g_WTk[DMODEL * DMODEL];
__device__ float g_WTv[DMODEL * DMODEL];
__device__ float g_WTo[DMODEL * DMODEL];

__device__ __forceinline__ uint32_t f2tf32(float f) {
    uint32_t r;
    asm("cvt.rna.tf32.f32 %0, %1;" : "=r"(r) : "f"(f));
    return r;
}
__device__ __forceinline__ float rndtf(float f) { return __uint_as_float(f2tf32(f)); }

#define MMA_TF32(C, A, B0, B1)                                              \
    asm volatile(                                                           \
        "mma.sync.aligned.m16n8k8.row.col.f32.tf32.tf32.f32 "               \
        "{%0,%1,%2,%3}, {%4,%5,%6,%7}, {%8,%9}, {%0,%1,%2,%3};"             \
        : "+f"((C)[0]), "+f"((C)[1]), "+f"((C)[2]), "+f"((C)[3])            \
        : "r"((A)[0]), "r"((A)[1]), "r"((A)[2]), "r"((A)[3]),               \
          "r"(B0), "r"(B1))

#define CP_ASYNC16(dst, src)                                                \
    asm volatile("cp.async.ca.shared.global [%0], [%1], 16;"                \
                 :: "r"(dst), "l"(src))
#define CP_COMMIT()  asm volatile("cp.async.commit_group;" ::: "memory")
#define CP_WAIT(n)   asm volatile("cp.async.wait_group %0;" :: "n"(n) : "memory")

#define LDSM4(R, addr)                                                      \
    asm volatile("ldmatrix.sync.aligned.m8n8.x4.shared.b16 "                \
                 "{%0,%1,%2,%3}, [%4];"                                     \
                 : "=r"((R)[0]), "=r"((R)[1]), "=r"((R)[2]), "=r"((R)[3])   \
                 : "r"(addr))

extern __shared__ uint32_t dsm[];

// ---------------------------------------------------------------------------
// Pre-pass 1: round Q/K/V inputs to tf32 in gmem (blockIdx.y selects tensor)
// ---------------------------------------------------------------------------
__global__ __launch_bounds__(256) void prep_round_kernel(
    const float4* __restrict__ xq, const float4* __restrict__ xk,
    const float4* __restrict__ xv,
    float4* __restrict__ oq, float4* __restrict__ ok, float4* __restrict__ ov) {
    const int i = blockIdx.x * 256 + threadIdx.x;   // MTOT*DMODEL/4 = 1048576
    const float4* in  = blockIdx.y == 0 ? xq : blockIdx.y == 1 ? xk : xv;
    float4*       out = blockIdx.y == 0 ? oq : blockIdx.y == 1 ? ok : ov;
    float4 v = in[i];
    out[i] = make_float4(rndtf(v.x), rndtf(v.y), rndtf(v.z), rndtf(v.w));
}

// ---------------------------------------------------------------------------
// Pre-pass 2: W[k][n] -> W^T[n][k], tf32-rounded (blockIdx.z selects matrix)
// ---------------------------------------------------------------------------
__global__ void transpose_round_kernel(
    const float* __restrict__ Wq, const float* __restrict__ Wk,
    const float* __restrict__ Wv, const float* __restrict__ Wo,
    float* __restrict__ Tq, float* __restrict__ Tk,
    float* __restrict__ Tv, float* __restrict__ To) {
    __shared__ float tile[32][33];
    const int z = blockIdx.z;
    const float* W = z == 0 ? Wq : z == 1 ? Wk : z == 2 ? Wv : Wo;
    float*       T = z == 0 ? Tq : z == 1 ? Tk : z == 2 ? Tv : To;
    const int tx = threadIdx.x, ty = threadIdx.y;
    const int bx = blockIdx.x * 32, by = blockIdx.y * 32;
#pragma unroll
    for (int i = 0; i < 4; i++)
        tile[ty + i * 8][tx] = W[(size_t)(by + ty + i * 8) * DMODEL + bx + tx];
    __syncthreads();
#pragma unroll
    for (int i = 0; i < 4; i++)
        T[(size_t)(bx + ty + i * 8) * DMODEL + by + tx] =
            rndtf(tile[tx][ty + i * 8]);
}

// ---------------------------------------------------------------------------
// tf32 GEMM v2: out[m][n] = X[m][:] @ W^T[n][:] + bias[n]
// Both operands pre-rounded tf32 bits, K-major in gmem.
// 128x128x16 tile, 8 warps (2m x 4n), warp tile 64x32, 4-stage cp.async,
// XOR-swizzled smem (chunk ^ row&3), ldmatrix.x4 for A and B fragments.
// mode 0: scatter tf32-rounded to head-major [b,h,s,d]; mode 1: fp32 [m][n].
// ---------------------------------------------------------------------------
#define GSTAGE_BYTES 16384            // A 8KB + B 8KB
#define GEMM_SMEM_BYTES (4 * GSTAGE_BYTES)   // 65536

__device__ __forceinline__ void gemm_body2(
    const float* __restrict__ X, const float* __restrict__ WT,
    const float* __restrict__ bias, float* __restrict__ out, int mode) {
    const int tid  = threadIdx.x;
    const int lane = tid & 31;
    const int warp = tid >> 5;
    const int g = lane >> 2, t = lane & 3;
    const int wm = (warp & 1) * 64;
    const int wn = (warp >> 1) * 32;
    const int m0 = blockIdx.y * 128;
    const int n0 = blockIdx.x * 128;

    const uint32_t smem_u = (uint32_t)__cvta_generic_to_shared(dsm);

    // cp.async chunk mapping: chunk c -> row c>>2, 16B piece kc = c&3,
    // swizzled to column kc ^ (row&3). 512 chunks per operand per stage.
    const int cm[2] = { tid >> 2, (tid + 256) >> 2 };
    const int kc2   = tid & 3;
    const float* Xp = X  + (size_t)m0 * DMODEL;
    const float* Wp = WT + (size_t)n0 * DMODEL;

    // ldmatrix per-thread address offsets
    const int j = lane >> 3, r = lane & 7;
    const int mrow = wm + (j & 1) * 8 + r;            // A: tiles 0/1 rows, 2/3 k+4
    const int nrow = wn + (j >> 1) * 8 + r;           // B: tiles 0/1 k, 2/3 n+8
    uint32_t aoff[2], boff[2];
#pragma unroll
    for (int ks = 0; ks < 2; ks++) {
        const int kca = ks * 2 + (j >> 1);
        aoff[ks] = (uint32_t)(mrow * 64 + ((kca ^ (mrow & 3)) << 4));
        const int kcb = ks * 2 + (j & 1);
        boff[ks] = (uint32_t)(8192 + nrow * 64 + ((kcb ^ (nrow & 3)) << 4));
    }

    float c[4][4][4];
#pragma unroll
    for (int mt = 0; mt < 4; mt++)
#pragma unroll
        for (int ni = 0; ni < 4; ni++)
#pragma unroll
            for (int q = 0; q < 4; q++) c[mt][ni][q] = 0.f;

    // Prologue: stages 0..2
#pragma unroll
    for (int s = 0; s < 3; s++) {
        const uint32_t sb = smem_u + s * GSTAGE_BYTES;
        const int k0 = s * 16;
#pragma unroll
        for (int i = 0; i < 2; i++) {
            const int m = cm[i];
            const uint32_t sw = (uint32_t)(m * 64 + ((kc2 ^ (m & 3)) << 4));
            CP_ASYNC16(sb + sw,        Xp + (size_t)m * DMODEL + k0 + kc2 * 4);
            CP_ASYNC16(sb + 8192 + sw, Wp + (size_t)m * DMODEL + k0 + kc2 * 4);
        }
        CP_COMMIT();
    }

    const int NITER = DMODEL / 16;   // 64
    for (int it = 0; it < NITER; it++) {
        CP_WAIT(2);          // tile `it` has landed
        __syncthreads();     // all warps past compute(it-1); data visible
        const uint32_t sb = smem_u + (it & 3) * GSTAGE_BYTES;

#pragma unroll
        for (int ks = 0; ks < 2; ks++) {
            uint32_t a[4][4];
#pragma unroll
            for (int mt = 0; mt < 4; mt++)
                LDSM4(a[mt], sb + mt * 1024 + aoff[ks]);
            uint32_t bf[2][4];   // [nq]: {b0 ni=2nq, b1 ni=2nq, b0 ni=2nq+1, b1 ni=2nq+1}
#pragma unroll
            for (int nq = 0; nq < 2; nq++)
                LDSM4(bf[nq], sb + nq * 1024 + boff[ks]);
#pragma unroll
            for (int mt = 0; mt < 4; mt++)
#pragma unroll
                for (int ni = 0; ni < 4; ni++)
                    MMA_TF32(c[mt][ni], a[mt],
                             bf[ni >> 1][(ni & 1) * 2],
                             bf[ni >> 1][(ni & 1) * 2 + 1]);
        }

        if (it + 3 < NITER) {
            const uint32_t sb2 = smem_u + ((it + 3) & 3) * GSTAGE_BYTES;
            const int k0 = (it + 3) * 16;
#pragma unroll
            for (int i = 0; i < 2; i++) {
                const int m = cm[i];
                const uint32_t sw = (uint32_t)(m * 64 + ((kc2 ^ (m & 3)) << 4));
                CP_ASYNC16(sb2 + sw,        Xp + (size_t)m * DMODEL + k0 + kc2 * 4);
                CP_ASYNC16(sb2 + 8192 + sw, Wp + (size_t)m * DMODEL + k0 + kc2 * 4);
            }
        }
        CP_COMMIT();         // always: keeps wait_group arithmetic exact
    }

    // Epilogue
#pragma unroll
    for (int ni = 0; ni < 4; ni++) {
        const int col = n0 + wn + ni * 8 + 2 * t;
        const float2 bb = *(const float2*)(bias + col);
#pragma unroll
        for (int mt = 0; mt < 4; mt++) {
            const int row0 = m0 + wm + mt * 16 + g;
#pragma unroll
            for (int half = 0; half < 2; half++) {
                const int m = row0 + half * 8;
                float2 rr;
                rr.x = c[mt][ni][half * 2 + 0] + bb.x;
                rr.y = c[mt][ni][half * 2 + 1] + bb.y;
                if (mode == 0) {
                    rr.x = rndtf(rr.x);
                    rr.y = rndtf(rr.y);
                    const int b = m >> 11, s = m & 2047;
                    const int h = col >> 6, d = col & 63;
                    *(float2*)(out + (((size_t)b * NHEADS + h) * SEQ + s) * HDIM + d) = rr;
                } else {
                    *(float2*)(out + (size_t)m * DMODEL + col) = rr;
                }
            }
        }
    }
}

__global__ __launch_bounds__(256, 2) void gemm_tf32_kernel(
    const float* __restrict__ X, const float* __restrict__ WT,
    const float* __restrict__ bias, float* __restrict__ out, int mode) {
    gemm_body2(X, WT, bias, out, mode);
}

__global__ __launch_bounds__(256, 2) void gemm_qkv_kernel(
    const float* __restrict__ xq, const float* __restrict__ xk, const float* __restrict__ xv,
    const float* __restrict__ wq, const float* __restrict__ wk, const float* __restrict__ wv,
    const float* __restrict__ bq, const float* __restrict__ bk, const float* __restrict__ bv,
    float* __restrict__ oq, float* __restrict__ ok, float* __restrict__ ov) {
    const int z = blockIdx.z;
    const float* X = (z == 0) ? xq : (z == 1) ? xk : xv;
    const float* W = (z == 0) ? wq : (z == 1) ? wk : wv;
    const float* B = (z == 0) ? bq : (z == 1) ? bk : bv;
    float*       O = (z == 0) ? oq : (z == 1) ? ok : ov;
    gemm_body2(X, W, B, O, 0);
}

// ---------------------------------------------------------------------------
// tf32 tensor-core flash attention, cp.async double-buffered K/V pipeline.
// (unchanged from round 9 except epilogue rounds output to tf32 for the
//  out-projection GEMM — same cvt.rna, same dataflow point as before.)
// ---------------------------------------------------------------------------
#define BQ 64
#define BK 64
#define SKK 68
#define SKV 72
#define KW   (BK * SKK)
#define VW   (BK * SKV)
#define STAGEW (KW + VW)
#define ATTN_SMEM_BYTES (2 * STAGEW * 4)   // 71680

__global__ __launch_bounds__(128, 3) void attn_tf32_kernel(
    const float* __restrict__ Q, const float* __restrict__ K,
    const float* __restrict__ V, float* __restrict__ Out) {
    const int tid  = threadIdx.x;
    const int lane = tid & 31;
    const int warp = tid >> 5;
    const int g = lane >> 2;
    const int t = lane & 3;
    const int q0 = blockIdx.x * BQ;
    const int h  = blockIdx.y;
    const int b  = blockIdx.z;
    const size_t bh = (size_t)b * NHEADS + h;
    const float* Qb = Q + bh * SEQ * HDIM;
    const float* Kb = K + bh * SEQ * HDIM;
    const float* Vb = V + bh * SEQ * HDIM;

    uint32_t qa[8][4];
    {
        const float* Qw = Qb + (size_t)(q0 + warp * 16) * HDIM;
#pragma unroll
        for (int ks = 0; ks < 8; ks++) {
            qa[ks][0] = __float_as_uint(0.125f * Qw[g       * HDIM + 8 * ks + t]);
            qa[ks][1] = __float_as_uint(0.125f * Qw[(g + 8) * HDIM + 8 * ks + t]);
            qa[ks][2] = __float_as_uint(0.125f * Qw[g       * HDIM + 8 * ks + t + 4]);
            qa[ks][3] = __float_as_uint(0.125f * Qw[(g + 8) * HDIM + 8 * ks + t + 4]);
        }
    }

    float o[8][4];
#pragma unroll
    for (int ni = 0; ni < 8; ni++)
#pragma unroll
        for (int rq = 0; rq < 4; rq++) o[ni][rq] = 0.f;
    float m0 = -1e30f, m1 = -1e30f, l0 = 0.f, l1 = 0.f;

    const int qb = lane & ~3;
    const int s0 = qb + (t >> 1);
    const int s1 = s0 + 2;

    auto stage_tile = [&](int stage, int kt) {
        uint32_t* sK = dsm + stage * STAGEW;
        uint32_t* sV = sK + KW;
        const float* Kg = Kb + (size_t)kt * HDIM;
        const float* Vg = Vb + (size_t)kt * HDIM;
#pragma unroll
        for (int i = 0; i < 8; i++) {
            const int idx = tid + i * 128;
            const int rr = idx >> 4;
            const int c4 = (idx & 15) * 4;
            unsigned dk = (unsigned)__cvta_generic_to_shared(&sK[rr * SKK + c4]);
            CP_ASYNC16(dk, Kg + (size_t)rr * HDIM + c4);
            unsigned dv = (unsigned)__cvta_generic_to_shared(&sV[rr * SKV + c4]);
            CP_ASYNC16(dv, Vg + (size_t)rr * HDIM + c4);
        }
    };

    stage_tile(0, 0);
    CP_COMMIT();

    int buf = 0;
    for (int kt = 0; kt < SEQ; kt += BK) {
        if (kt + BK < SEQ) {
            stage_tile(buf ^ 1, kt + BK);
            CP_COMMIT();
            CP_WAIT(1);
        } else {
            CP_WAIT(0);
        }
        __syncthreads();

        const uint32_t* sK = dsm + buf * STAGEW;
        const uint32_t* sV = sK + KW;

        float c[8][4];
#pragma unroll
        for (int ni = 0; ni < 8; ni++) {
            c[ni][0] = c[ni][1] = c[ni][2] = c[ni][3] = 0.f;
            const uint32_t* kcol = &sK[(ni * 8 + g) * SKK];
#pragma unroll
            for (int ks = 0; ks < 8; ks++) {
                const uint32_t b0 = kcol[8 * ks + t];
                const uint32_t b1 = kcol[8 * ks + t + 4];
                MMA_TF32(c[ni], qa[ks], b0, b1);
            }
        }

        float pm0 = c[0][0], pm1 = c[0][2];
#pragma unroll
        for (int ni = 0; ni < 8; ni++) {
            pm0 = fmaxf(pm0, fmaxf(c[ni][0], c[ni][1]));
            pm1 = fmaxf(pm1, fmaxf(c[ni][2], c[ni][3]));
        }
        pm0 = fmaxf(pm0, __shfl_xor_sync(0xffffffffu, pm0, 1));
        pm0 = fmaxf(pm0, __shfl_xor_sync(0xffffffffu, pm0, 2));
        pm1 = fmaxf(pm1, __shfl_xor_sync(0xffffffffu, pm1, 1));
        pm1 = fmaxf(pm1, __shfl_xor_sync(0xffffffffu, pm1, 2));

        const float mn0 = fmaxf(m0, pm0);
        const float mn1 = fmaxf(m1, pm1);
        float rs0 = 0.f, rs1 = 0.f;
#pragma unroll
        for (int ni = 0; ni < 8; ni++) {
            c[ni][0] = __expf(c[ni][0] - mn0);
            c[ni][1] = __expf(c[ni][1] - mn0);
            c[ni][2] = __expf(c[ni][2] - mn1);
            c[ni][3] = __expf(c[ni][3] - mn1);
            rs0 += c[ni][0] + c[ni][1];
            rs1 += c[ni][2] + c[ni][3];
        }
        rs0 += __shfl_xor_sync(0xffffffffu, rs0, 1);
        rs0 += __shfl_xor_sync(0xffffffffu, rs0, 2);
        rs1 += __shfl_xor_sync(0xffffffffu, rs1, 1);
        rs1 += __shfl_xor_sync(0xffffffffu, rs1, 2);

        const float alpha0 = __expf(m0 - mn0);
        const float alpha1 = __expf(m1 - mn1);
        l0 = l0 * alpha0 + rs0;  m0 = mn0;
        l1 = l1 * alpha1 + rs1;  m1 = mn1;
#pragma unroll
        for (int ni = 0; ni < 8; ni++) {
            o[ni][0] *= alpha0; o[ni][1] *= alpha0;
            o[ni][2] *= alpha1; o[ni][3] *= alpha1;
        }

        uint32_t pa[8][4];
#pragma unroll
        for (int jj = 0; jj < 8; jj++) {
            const float v00 = __shfl_sync(0xffffffffu, c[jj][0], s0);
            const float v01 = __shfl_sync(0xffffffffu, c[jj][1], s0);
            const float v02 = __shfl_sync(0xffffffffu, c[jj][0], s1);
            const float v03 = __shfl_sync(0xffffffffu, c[jj][1], s1);
            const float v10 = __shfl_sync(0xffffffffu, c[jj][2], s0);
            const float v11 = __shfl_sync(0xffffffffu, c[jj][3], s0);
            const float v12 = __shfl_sync(0xffffffffu, c[jj][2], s1);
            const float v13 = __shfl_sync(0xffffffffu, c[jj][3], s1);
            pa[jj][0] = f2tf32((t & 1) ? v01 : v00);
            pa[jj][1] = f2tf32((t & 1) ? v11 : v10);
            pa[jj][2] = f2tf32((t & 1) ? v03 : v02);
            pa[jj][3] = f2tf32((t & 1) ? v13 : v12);
        }

#pragma unroll
        for (int jj = 0; jj < 8; jj++) {
#pragma unroll
            for (int ni = 0; ni < 8; ni++) {
                const uint32_t b0 = sV[(8 * jj + t    ) * SKV + ni * 8 + g];
                const uint32_t b1 = sV[(8 * jj + t + 4) * SKV + ni * 8 + g];
                MMA_TF32(o[ni], pa[jj], b0, b1);
            }
        }

        __syncthreads();
        buf ^= 1;
    }

    const float inv0 = 1.0f / l0;
    const float inv1 = 1.0f / l1;
    const int r0 = q0 + warp * 16 + g;
    const int r1 = r0 + 8;
#pragma unroll
    for (int ni = 0; ni < 8; ni++) {
        const int col = h * HDIM + ni * 8 + 2 * t;
        float2 w0 = make_float2(rndtf(o[ni][0] * inv0), rndtf(o[ni][1] * inv0));
        float2 w1 = make_float2(rndtf(o[ni][2] * inv1), rndtf(o[ni][3] * inv1));
        *(float2*)(Out + ((size_t)b * SEQ + r0) * DMODEL + col) = w0;
        *(float2*)(Out + ((size_t)b * SEQ + r1) * DMODEL + col) = w1;
    }
}

// ---------------------------------------------------------------------------
extern "C" void kernel_launch(void* const* d_in, const int* in_sizes, int n_in,
                              void* d_out, int out_size) {
    const float* q  = (const float*)d_in[0];
    const float* k  = (const float*)d_in[1];
    const float* v  = (const float*)d_in[2];
    const float* Wq = (const float*)d_in[3];
    const float* bq = (const float*)d_in[4];
    const float* Wk = (const float*)d_in[5];
    const float* bk = (const float*)d_in[6];
    const float* Wv = (const float*)d_in[7];
    const float* bv = (const float*)d_in[8];
    const float* Wo = (const float*)d_in[9];
    const float* bo = (const float*)d_in[10];
    float* out = (float*)d_out;

    float *gq, *gk, *gv, *ga, *xq, *xk, *xv, *wtq, *wtk, *wtv, *wto;
    cudaGetSymbolAddress((void**)&gq,  g_Q);
    cudaGetSymbolAddress((void**)&gk,  g_K);
    cudaGetSymbolAddress((void**)&gv,  g_V);
    cudaGetSymbolAddress((void**)&ga,  g_attn);
    cudaGetSymbolAddress((void**)&xq,  g_Xq);
    cudaGetSymbolAddress((void**)&xk,  g_Xk);
    cudaGetSymbolAddress((void**)&xv,  g_Xv);
    cudaGetSymbolAddress((void**)&wtq, g_WTq);
    cudaGetSymbolAddress((void**)&wtk, g_WTk);
    cudaGetSymbolAddress((void**)&wtv, g_WTv);
    cudaGetSymbolAddress((void**)&wto, g_WTo);

    static bool attr_done = false;
    if (!attr_done) {
        cudaFuncSetAttribute(attn_tf32_kernel,
                             cudaFuncAttributeMaxDynamicSharedMemorySize,
                             ATTN_SMEM_BYTES);
        cudaFuncSetAttribute(gemm_tf32_kernel,
                             cudaFuncAttributeMaxDynamicSharedMemorySize,
                             GEMM_SMEM_BYTES);
        cudaFuncSetAttribute(gemm_qkv_kernel,
                             cudaFuncAttributeMaxDynamicSharedMemorySize,
                             GEMM_SMEM_BYTES);
        attr_done = true;
    }

    // Pre-pass: round inputs, transpose+round weights
    prep_round_kernel<<<dim3(MTOT * DMODEL / 4 / 256, 3), 256>>>(
        (const float4*)q, (const float4*)k, (const float4*)v,
        (float4*)xq, (float4*)xk, (float4*)xv);
    transpose_round_kernel<<<dim3(32, 32, 4), dim3(32, 8)>>>(
        Wq, Wk, Wv, Wo, wtq, wtk, wtv, wto);

    // Fused Q/K/V projections
    dim3 qkv_grid(DMODEL / 128, MTOT / 128, 3);
    gemm_qkv_kernel<<<qkv_grid, dim3(256), GEMM_SMEM_BYTES>>>(
        xq, xk, xv, wtq, wtk, wtv, bq, bk, bv, gq, gk, gv);

    dim3 attn_grid(SEQ / BQ, NHEADS, BATCH);
    attn_tf32_kernel<<<attn_grid, dim3(128), ATTN_SMEM_BYTES>>>(gq, gk, gv, ga);

    dim3 gemm_grid(DMODEL / 128, MTOT / 128);
    gemm_tf32_kernel<<<gemm_grid, dim3(256), GEMM_SMEM_BYTES>>>(ga, wto, bo, out, 1);
}

// round 15
// speedup vs baseline: 1.1683x; 1.1683x over previous
#include <cuda_runtime.h>
#include <cuda_bf16.h>
#include <cstdint>

// Problem constants
#define BATCH   2
#define SEQ     2048
#define DMODEL  1024
#define NHEADS  16
#define HDIM    64
#define MTOT    (BATCH * SEQ)          // 4096

// Scratch (device globals; no allocations allowed)
// Q/K/V hold tf32-rounded fp32 bit patterns (written by projection epilogue).
__device__ float g_Q[BATCH * NHEADS * SEQ * HDIM];     // [b,h,s,d]  16 MB
__device__ float g_K[BATCH * NHEADS * SEQ * HDIM];
__device__ float g_V[BATCH * NHEADS * SEQ * HDIM];
__device__ float g_attn[MTOT * DMODEL];                // [b*s, h*d] 16 MB

__device__ __forceinline__ uint32_t f2tf32(float f) {
    uint32_t r;
    asm("cvt.rna.tf32.f32 %0, %1;" : "=r"(r) : "f"(f));
    return r;
}

#define MMA_TF32(C, A, B0, B1)                                              \
    asm volatile(                                                           \
        "mma.sync.aligned.m16n8k8.row.col.f32.tf32.tf32.f32 "               \
        "{%0,%1,%2,%3}, {%4,%5,%6,%7}, {%8,%9}, {%0,%1,%2,%3};"             \
        : "+f"((C)[0]), "+f"((C)[1]), "+f"((C)[2]), "+f"((C)[3])            \
        : "r"((A)[0]), "r"((A)[1]), "r"((A)[2]), "r"((A)[3]),               \
          "r"(B0), "r"(B1))

#define CP_ASYNC16(dst, src)                                                \
    asm volatile("cp.async.ca.shared.global [%0], [%1], 16;"                \
                 :: "r"(dst), "l"(src))
#define CP_COMMIT()  asm volatile("cp.async.commit_group;" ::: "memory")
#define CP_WAIT(n)   asm volatile("cp.async.wait_group %0;" :: "n"(n) : "memory")

#define LDSM4(R, addr)                                                      \
    asm volatile("ldmatrix.sync.aligned.m8n8.x4.shared.b16 "                \
                 "{%0,%1,%2,%3}, [%4];"                                     \
                 : "=r"((R)[0]), "=r"((R)[1]), "=r"((R)[2]), "=r"((R)[3])   \
                 : "r"(addr))

// ---------------------------------------------------------------------------
// tf32 tensor-core GEMM body: out[m][n] = X[m][:] @ W[:][n] + bias[n]
// 128x128x16 tile, 8 warps (4x2), warp 32x64 via m16n8k8, double-buffered.
// A-fragments via ldmatrix.x4 (stride-20 layout is conflict-free for the
// 8-rows-x-16B tile pattern); B-fragments scalar as before.
// mode 0: scatter tf32-ROUNDED to head-major [b,h,s,d]; mode 1: fp32 [m][n].
// ---------------------------------------------------------------------------
#define SA 20
#define SB 136

__device__ __forceinline__ void gemm_body(
    const float* __restrict__ X, const float* __restrict__ W,
    const float* __restrict__ bias, float* __restrict__ out, int mode) {
    __shared__ uint32_t As[2][128][SA];   // [m][k]
    __shared__ uint32_t Bs[2][16][SB];    // [k][n]

    const int tid  = threadIdx.x;
    const int lane = tid & 31;
    const int warp = tid >> 5;
    const int g = lane >> 2;
    const int t = lane & 3;
    const int wm = (warp >> 1) * 32;
    const int wn = (warp & 1) * 64;
    const int m0 = blockIdx.y * 128;
    const int n0 = blockIdx.x * 128;

    const int am[2]  = { tid >> 2, (tid + 256) >> 2 };
    const int ak[2]  = { (tid & 3) * 4, (tid & 3) * 4 };
    const int bk[2]  = { tid >> 5, (tid + 256) >> 5 };
    const int bn[2]  = { (tid & 31) * 4, (tid & 31) * 4 };

    // ldmatrix thread->address mapping for A fragments:
    // tile j>>3: rows +((j>>3)&1)*8, col +(j>>4)*4  ->  regs = a0..a3
    const int arow  = (lane & 7) + ((lane >> 3) & 1) * 8;
    const int acol4 = (lane >> 4) * 4;
    const uint32_t As_u = (uint32_t)__cvta_generic_to_shared(&As[0][0][0]);

    const float* Xp = X + (size_t)m0 * DMODEL;
    const float* Wp = W + n0;

    float c[2][8][4];
#pragma unroll
    for (int mt = 0; mt < 2; mt++)
#pragma unroll
        for (int ni = 0; ni < 8; ni++)
#pragma unroll
            for (int r = 0; r < 4; r++) c[mt][ni][r] = 0.f;

    float4 ra[2], rb[2];

#pragma unroll
    for (int i = 0; i < 2; i++) {
        ra[i] = *(const float4*)(Xp + (size_t)am[i] * DMODEL + ak[i]);
        rb[i] = *(const float4*)(Wp + (size_t)bk[i] * DMODEL + bn[i]);
    }
#pragma unroll
    for (int i = 0; i < 2; i++) {
        uint32_t* ap = &As[0][am[i]][ak[i]];
        ap[0] = f2tf32(ra[i].x); ap[1] = f2tf32(ra[i].y);
        ap[2] = f2tf32(ra[i].z); ap[3] = f2tf32(ra[i].w);
        uint32_t* bp = &Bs[0][bk[i]][bn[i]];
        bp[0] = f2tf32(rb[i].x); bp[1] = f2tf32(rb[i].y);
        bp[2] = f2tf32(rb[i].z); bp[3] = f2tf32(rb[i].w);
    }
    __syncthreads();

    int buf = 0;
    const int NITER = DMODEL / 16;   // 64
    for (int it = 0; it < NITER; it++) {
        const int k_next = (it + 1) * 16;
        if (it + 1 < NITER) {
#pragma unroll
            for (int i = 0; i < 2; i++) {
                ra[i] = *(const float4*)(Xp + (size_t)am[i] * DMODEL + k_next + ak[i]);
                rb[i] = *(const float4*)(Wp + (size_t)(k_next + bk[i]) * DMODEL + bn[i]);
            }
        }

#pragma unroll
        for (int ks = 0; ks < 2; ks++) {
            const int kk = ks * 8;
            uint32_t a[2][4];
#pragma unroll
            for (int mt = 0; mt < 2; mt++) {
                const uint32_t addr = As_u +
                    (uint32_t)(((buf * 128 + wm + mt * 16 + arow) * SA + kk + acol4) * 4);
                LDSM4(a[mt], addr);
            }
#pragma unroll
            for (int ni = 0; ni < 8; ni++) {
                const uint32_t b0 = Bs[buf][kk + t    ][wn + ni * 8 + g];
                const uint32_t b1 = Bs[buf][kk + t + 4][wn + ni * 8 + g];
#pragma unroll
                for (int mt = 0; mt < 2; mt++) {
                    MMA_TF32(c[mt][ni], a[mt], b0, b1);
                }
            }
        }

        if (it + 1 < NITER) {
            const int nb = buf ^ 1;
#pragma unroll
            for (int i = 0; i < 2; i++) {
                uint32_t* ap = &As[nb][am[i]][ak[i]];
                ap[0] = f2tf32(ra[i].x); ap[1] = f2tf32(ra[i].y);
                ap[2] = f2tf32(ra[i].z); ap[3] = f2tf32(ra[i].w);
                uint32_t* bp = &Bs[nb][bk[i]][bn[i]];
                bp[0] = f2tf32(rb[i].x); bp[1] = f2tf32(rb[i].y);
                bp[2] = f2tf32(rb[i].z); bp[3] = f2tf32(rb[i].w);
            }
            __syncthreads();
            buf = nb;
        }
    }

#pragma unroll
    for (int ni = 0; ni < 8; ni++) {
        const int col = n0 + wn + ni * 8 + 2 * t;
        const float2 bb = *(const float2*)(bias + col);
#pragma unroll
        for (int mt = 0; mt < 2; mt++) {
            const int row0 = m0 + wm + mt * 16 + g;
#pragma unroll
            for (int half = 0; half < 2; half++) {
                const int m = row0 + half * 8;
                float2 r;
                r.x = c[mt][ni][half * 2 + 0] + bb.x;
                r.y = c[mt][ni][half * 2 + 1] + bb.y;
                if (mode == 0) {
                    // tf32-round at write: consumer (attn) uses bits directly
                    r.x = __uint_as_float(f2tf32(r.x));
                    r.y = __uint_as_float(f2tf32(r.y));
                    const int b = m >> 11, s = m & 2047;
                    const int h = col >> 6, d = col & 63;
                    *(float2*)(out + (((size_t)b * NHEADS + h) * SEQ + s) * HDIM + d) = r;
                } else {
                    *(float2*)(out + (size_t)m * DMODEL + col) = r;
                }
            }
        }
    }
}

__global__ __launch_bounds__(256, 2) void gemm_tf32_kernel(
    const float* __restrict__ X, const float* __restrict__ W,
    const float* __restrict__ bias, float* __restrict__ out, int mode) {
    gemm_body(X, W, bias, out, mode);
}

// Fused Q/K/V projections: blockIdx.z selects operand set (one launch, 768 CTAs)
__global__ __launch_bounds__(256, 2) void gemm_qkv_kernel(
    const float* __restrict__ xq, const float* __restrict__ xk, const float* __restrict__ xv,
    const float* __restrict__ Wq, const float* __restrict__ Wk, const float* __restrict__ Wv,
    const float* __restrict__ bq, const float* __restrict__ bk, const float* __restrict__ bv,
    float* __restrict__ oq, float* __restrict__ ok, float* __restrict__ ov) {
    const int z = blockIdx.z;
    const float* X = (z == 0) ? xq : (z == 1) ? xk : xv;
    const float* W = (z == 0) ? Wq : (z == 1) ? Wk : Wv;
    const float* B = (z == 0) ? bq : (z == 1) ? bk : bv;
    float*       O = (z == 0) ? oq : (z == 1) ? ok : ov;
    gemm_body(X, W, B, O, 0);
}

// ---------------------------------------------------------------------------
// tf32 tensor-core flash attention, cp.async double-buffered K/V pipeline.
// Block = 64 q-rows x (head, batch); 128 threads (4 warps x 16 rows),
// 3 CTAs/SM. S-phase K fragments via ldmatrix.x4 (stride 68 -> rows at
// banks r*4, conflict-free). V-phase scalar (would need V^T for ldmatrix).
// ---------------------------------------------------------------------------
#define BQ 64
#define BK 64
#define SKK 68
#define SKV 72
#define KW   (BK * SKK)
#define VW   (BK * SKV)
#define STAGEW (KW + VW)
#define ATTN_SMEM_BYTES (2 * STAGEW * 4)   // 71680

extern __shared__ uint32_t dsm[];

__global__ __launch_bounds__(128, 3) void attn_tf32_kernel(
    const float* __restrict__ Q, const float* __restrict__ K,
    const float* __restrict__ V, float* __restrict__ Out) {
    const int tid  = threadIdx.x;
    const int lane = tid & 31;
    const int warp = tid >> 5;
    const int g = lane >> 2;
    const int t = lane & 3;
    const int q0 = blockIdx.x * BQ;
    const int h  = blockIdx.y;
    const int b  = blockIdx.z;
    const size_t bh = (size_t)b * NHEADS + h;
    const float* Qb = Q + bh * SEQ * HDIM;
    const float* Kb = K + bh * SEQ * HDIM;
    const float* Vb = V + bh * SEQ * HDIM;

    const uint32_t dsm_u = (uint32_t)__cvta_generic_to_shared(dsm);

    // Q fragments: gmem holds tf32 bits; x0.125 is exact -> use bits directly.
    uint32_t qa[8][4];
    {
        const float* Qw = Qb + (size_t)(q0 + warp * 16) * HDIM;
#pragma unroll
        for (int ks = 0; ks < 8; ks++) {
            qa[ks][0] = __float_as_uint(0.125f * Qw[g       * HDIM + 8 * ks + t]);
            qa[ks][1] = __float_as_uint(0.125f * Qw[(g + 8) * HDIM + 8 * ks + t]);
            qa[ks][2] = __float_as_uint(0.125f * Qw[g       * HDIM + 8 * ks + t + 4]);
            qa[ks][3] = __float_as_uint(0.125f * Qw[(g + 8) * HDIM + 8 * ks + t + 4]);
        }
    }

    float o[8][4];
#pragma unroll
    for (int ni = 0; ni < 8; ni++)
#pragma unroll
        for (int rq = 0; rq < 4; rq++) o[ni][rq] = 0.f;
    float m0 = -1e30f, m1 = -1e30f, l0 = 0.f, l1 = 0.f;

    const int qb = lane & ~3;
    const int s0 = qb + (t >> 1);
    const int s1 = s0 + 2;

    // ldmatrix thread->address mapping for K fragments (S phase):
    // tile j>>3 covers d-chunk (j>>3)*4 within a 16-d pair; rows = keys.
    const int krow  = lane & 7;
    const int kcol4 = (lane >> 3) * 4;

    auto stage_tile = [&](int stage, int kt) {
        uint32_t* sK = dsm + stage * STAGEW;
        uint32_t* sV = sK + KW;
        const float* Kg = Kb + (size_t)kt * HDIM;
        const float* Vg = Vb + (size_t)kt * HDIM;
#pragma unroll
        for (int i = 0; i < 8; i++) {
            const int idx = tid + i * 128;
            const int rr = idx >> 4;
            const int c4 = (idx & 15) * 4;
            unsigned dk = (unsigned)__cvta_generic_to_shared(&sK[rr * SKK + c4]);
            CP_ASYNC16(dk, Kg + (size_t)rr * HDIM + c4);
            unsigned dv = (unsigned)__cvta_generic_to_shared(&sV[rr * SKV + c4]);
            CP_ASYNC16(dv, Vg + (size_t)rr * HDIM + c4);
        }
    };

    stage_tile(0, 0);
    CP_COMMIT();

    int buf = 0;
    for (int kt = 0; kt < SEQ; kt += BK) {
        if (kt + BK < SEQ) {
            stage_tile(buf ^ 1, kt + BK);
            CP_COMMIT();
            CP_WAIT(1);
        } else {
            CP_WAIT(0);
        }
        __syncthreads();

        const uint32_t sKu = dsm_u + (uint32_t)(buf * STAGEW * 4);
        const uint32_t* sV = dsm + buf * STAGEW + KW;

        // S = (Q/8) @ K^T : K fragments via ldmatrix.x4
        float c[8][4];
#pragma unroll
        for (int ni = 0; ni < 8; ni++) {
            c[ni][0] = c[ni][1] = c[ni][2] = c[ni][3] = 0.f;
            const uint32_t rowbase = sKu +
                (uint32_t)(((ni * 8 + krow) * SKK + kcol4) * 4);
#pragma unroll
            for (int p = 0; p < 4; p++) {
                uint32_t bf[4];
                LDSM4(bf, rowbase + p * 64);   // 16 d-words per pair
                MMA_TF32(c[ni], qa[2 * p    ], bf[0], bf[1]);
                MMA_TF32(c[ni], qa[2 * p + 1], bf[2], bf[3]);
            }
        }

        // Online softmax (rows r0 = g, r1 = g+8 of this warp's 16 rows)
        float pm0 = c[0][0], pm1 = c[0][2];
#pragma unroll
        for (int ni = 0; ni < 8; ni++) {
            pm0 = fmaxf(pm0, fmaxf(c[ni][0], c[ni][1]));
            pm1 = fmaxf(pm1, fmaxf(c[ni][2], c[ni][3]));
        }
        pm0 = fmaxf(pm0, __shfl_xor_sync(0xffffffffu, pm0, 1));
        pm0 = fmaxf(pm0, __shfl_xor_sync(0xffffffffu, pm0, 2));
        pm1 = fmaxf(pm1, __shfl_xor_sync(0xffffffffu, pm1, 1));
        pm1 = fmaxf(pm1, __shfl_xor_sync(0xffffffffu, pm1, 2));

        const float mn0 = fmaxf(m0, pm0);
        const float mn1 = fmaxf(m1, pm1);
        float rs0 = 0.f, rs1 = 0.f;
#pragma unroll
        for (int ni = 0; ni < 8; ni++) {
            c[ni][0] = __expf(c[ni][0] - mn0);
            c[ni][1] = __expf(c[ni][1] - mn0);
            c[ni][2] = __expf(c[ni][2] - mn1);
            c[ni][3] = __expf(c[ni][3] - mn1);
            rs0 += c[ni][0] + c[ni][1];
            rs1 += c[ni][2] + c[ni][3];
        }
        rs0 += __shfl_xor_sync(0xffffffffu, rs0, 1);
        rs0 += __shfl_xor_sync(0xffffffffu, rs0, 2);
        rs1 += __shfl_xor_sync(0xffffffffu, rs1, 1);
        rs1 += __shfl_xor_sync(0xffffffffu, rs1, 2);

        const float alpha0 = __expf(m0 - mn0);
        const float alpha1 = __expf(m1 - mn1);
        l0 = l0 * alpha0 + rs0;  m0 = mn0;
        l1 = l1 * alpha1 + rs1;  m1 = mn1;
#pragma unroll
        for (int ni = 0; ni < 8; ni++) {
            o[ni][0] *= alpha0; o[ni][1] *= alpha0;
            o[ni][2] *= alpha1; o[ni][3] *= alpha1;
        }

        // Relayout P: C-fragment (cols 2t,2t+1) -> A-fragment (cols t, t+4)
        uint32_t pa[8][4];
#pragma unroll
        for (int jj = 0; jj < 8; jj++) {
            const float v00 = __shfl_sync(0xffffffffu, c[jj][0], s0);
            const float v01 = __shfl_sync(0xffffffffu, c[jj][1], s0);
            const float v02 = __shfl_sync(0xffffffffu, c[jj][0], s1);
            const float v03 = __shfl_sync(0xffffffffu, c[jj][1], s1);
            const float v10 = __shfl_sync(0xffffffffu, c[jj][2], s0);
            const float v11 = __shfl_sync(0xffffffffu, c[jj][3], s0);
            const float v12 = __shfl_sync(0xffffffffu, c[jj][2], s1);
            const float v13 = __shfl_sync(0xffffffffu, c[jj][3], s1);
            pa[jj][0] = f2tf32((t & 1) ? v01 : v00);
            pa[jj][1] = f2tf32((t & 1) ? v11 : v10);
            pa[jj][2] = f2tf32((t & 1) ? v03 : v02);
            pa[jj][3] = f2tf32((t & 1) ? v13 : v12);
        }

        // O += P @ V
#pragma unroll
        for (int jj = 0; jj < 8; jj++) {
#pragma unroll
            for (int ni = 0; ni < 8; ni++) {
                const uint32_t b0 = sV[(8 * jj + t    ) * SKV + ni * 8 + g];
                const uint32_t b1 = sV[(8 * jj + t + 4) * SKV + ni * 8 + g];
                MMA_TF32(o[ni], pa[jj], b0, b1);
            }
        }

        __syncthreads();
        buf ^= 1;
    }

    const float inv0 = 1.0f / l0;
    const float inv1 = 1.0f / l1;
    const int r0 = q0 + warp * 16 + g;
    const int r1 = r0 + 8;
#pragma unroll
    for (int ni = 0; ni < 8; ni++) {
        const int col = h * HDIM + ni * 8 + 2 * t;
        float2 w0 = make_float2(o[ni][0] * inv0, o[ni][1] * inv0);
        float2 w1 = make_float2(o[ni][2] * inv1, o[ni][3] * inv1);
        *(float2*)(Out + ((size_t)b * SEQ + r0) * DMODEL + col) = w0;
        *(float2*)(Out + ((size_t)b * SEQ + r1) * DMODEL + col) = w1;
    }
}

// ---------------------------------------------------------------------------
extern "C" void kernel_launch(void* const* d_in, const int* in_sizes, int n_in,
                              void* d_out, int out_size) {
    const float* q  = (const float*)d_in[0];
    const float* k  = (const float*)d_in[1];
    const float* v  = (const float*)d_in[2];
    const float* Wq = (const float*)d_in[3];
    const float* bq = (const float*)d_in[4];
    const float* Wk = (const float*)d_in[5];
    const float* bk = (const float*)d_in[6];
    const float* Wv = (const float*)d_in[7];
    const float* bv = (const float*)d_in[8];
    const float* Wo = (const float*)d_in[9];
    const float* bo = (const float*)d_in[10];
    float* out = (float*)d_out;

    float *gq, *gk, *gv, *ga;
    cudaGetSymbolAddress((void**)&gq, g_Q);
    cudaGetSymbolAddress((void**)&gk, g_K);
    cudaGetSymbolAddress((void**)&gv, g_V);
    cudaGetSymbolAddress((void**)&ga, g_attn);

    static bool attr_done = false;
    if (!attr_done) {
        cudaFuncSetAttribute(attn_tf32_kernel,
                             cudaFuncAttributeMaxDynamicSharedMemorySize,
                             ATTN_SMEM_BYTES);
        attr_done = true;
    }

    // Fused Q/K/V projections: one launch, grid (8, 32, 3)
    dim3 qkv_grid(DMODEL / 128, MTOT / 128, 3);
    gemm_qkv_kernel<<<qkv_grid, dim3(256)>>>(q, k, v, Wq, Wk, Wv, bq, bk, bv, gq, gk, gv);

    dim3 attn_grid(SEQ / BQ, NHEADS, BATCH);    // (32, 16, 2) = 1024 CTAs
    attn_tf32_kernel<<<attn_grid, dim3(128), ATTN_SMEM_BYTES>>>(gq, gk, gv, ga);

    dim3 gemm_grid(DMODEL / 128, MTOT / 128);   // (8, 32)
    gemm_tf32_kernel<<<gemm_grid, dim3(256)>>>(ga, Wo, bo, out, 1);
}